// round 5
// baseline (speedup 1.0000x reference)
#include <cuda_runtime.h>

// Geometry fixed by the reference: (2,1,192,192,192) fp32 x3 -> scalar
constexpr int BATCH = 2, D = 192, H = 192, W = 192;
constexpr int DS = H * W;
constexpr int TX = 16, TY = 8, XV = 4;
constexpr int XSPAN = TX * XV;          // 64
constexpr int NXT = W / XSPAN;          // 3
constexpr int NYT = H / TY;             // 24
constexpr int ZC = 16, NZ = D / ZC;     // 12
constexpr int THREADS = TX * TY;        // 128
constexpr int ROWS = TY + 2;            // 10 (tile rows + y-halo)
constexpr int ROWF = 68;                // padded row pitch (floats) -> conflict-free
constexpr int ARR = ROWS * ROWF;        // 680
constexpr int BUF = 4 * ARR;            // sP,dP,sG,dG per plane buffer
constexpr long long NVOX = (long long)BATCH * D * H * W;
constexpr int NBLOCKS = NXT * NYT * NZ * BATCH;   // 1728
constexpr int NJOBS = 2 * ROWS * TX;    // 320 row-segment jobs per plane

__device__ double   g_accum = 0.0;
__device__ unsigned g_done  = 0;

__device__ __forceinline__ float fsqrt_a(float x) {
    float y; asm("sqrt.approx.f32 %0, %1;" : "=f"(y) : "f"(x)); return y;
}
__device__ __forceinline__ float htanh(float x) {
    float y; asm("tanh.approx.f32 %0, %1;" : "=f"(y) : "f"(x)); return y;
}

struct Fresh { float A[XV], Bx[XV], By[XV]; };
// streaming z-partials per image (24 regs):
//   Am/Ac = A[c-1], A[c];  Ux/Cx = Bx[c-1]+2Bx[c], Bx[c];  Uy/Cy likewise.
struct State { float Am[XV], Ac[XV], Ux[XV], Cx[XV], Uy[XV], Cy[XV]; };

// Producer: x-pass rows of plane zz for both images into smem buffer.
// Jobs flattened over all 128 threads (balanced across warps).
__device__ __forceinline__ void produce(float* __restrict__ buf,
                                        const float* __restrict__ P,
                                        const float* __restrict__ G,
                                        int zz, int by, int bx0, int tid) {
    const bool zok = (unsigned)zz < (unsigned)D;
#pragma unroll
    for (int jj = tid; jj < NJOBS; jj += THREADS) {
        int im = jj >= NJOBS / 2;
        int q  = jj - im * (NJOBS / 2);
        int r  = q >> 4, xg = q & 15;
        int gyr = by + r - 1;
        bool ok = zok && (unsigned)gyr < (unsigned)H;
        int gxl = bx0 + xg * XV;
        const float* p = (im ? G : P) + zz * DS + gyr * W + gxl;
        float v0 = 0.f, v1 = 0.f, v2 = 0.f, v3 = 0.f, vm = 0.f, vp = 0.f;
        if (ok) {
            float4 c4 = __ldg(reinterpret_cast<const float4*>(p));
            v0 = c4.x; v1 = c4.y; v2 = c4.z; v3 = c4.w;
            if (gxl > 0)      vm = __ldg(p - 1);
            if (gxl + XV < W) vp = __ldg(p + XV);
        }
        float* bs = buf + (2 * im) * ARR + r * ROWF + xg * XV;
        float4 s4 = make_float4(fmaf(2.f, v0, vm + v1), fmaf(2.f, v1, v0 + v2),
                                fmaf(2.f, v2, v1 + v3), fmaf(2.f, v3, v2 + vp));
        float4 d4 = make_float4(v1 - vm, v2 - v0, v3 - v1, vp - v2);
        *reinterpret_cast<float4*>(bs)       = s4;
        *reinterpret_cast<float4*>(bs + ARR) = d4;
    }
}

// Consumer: fold 3 smem rows (y-pass) for image im at this thread's tile cell.
__device__ __forceinline__ Fresh consume(const float* __restrict__ buf,
                                         int im, int ty, int tx) {
    const float* bs = buf + (2 * im) * ARR + ty * ROWF + tx * XV;
    float4 sa = *reinterpret_cast<const float4*>(bs);
    float4 sb = *reinterpret_cast<const float4*>(bs + ROWF);
    float4 sc = *reinterpret_cast<const float4*>(bs + 2 * ROWF);
    float4 da = *reinterpret_cast<const float4*>(bs + ARR);
    float4 db = *reinterpret_cast<const float4*>(bs + ARR + ROWF);
    float4 dc = *reinterpret_cast<const float4*>(bs + ARR + 2 * ROWF);
    Fresh f;
    float saj[4] = { sa.x, sa.y, sa.z, sa.w }, sbj[4] = { sb.x, sb.y, sb.z, sb.w };
    float scj[4] = { sc.x, sc.y, sc.z, sc.w };
    float daj[4] = { da.x, da.y, da.z, da.w }, dbj[4] = { db.x, db.y, db.z, db.w };
    float dcj[4] = { dc.x, dc.y, dc.z, dc.w };
#pragma unroll
    for (int j = 0; j < XV; j++) {
        f.A[j]  = fmaf(2.f, sbj[j], saj[j] + scj[j]);
        f.By[j] = saj[j] - scj[j];
        f.Bx[j] = fmaf(2.f, dbj[j], daj[j] + dcj[j]);
    }
    return f;
}

__device__ __forceinline__ void state_init(State& s, const Fresh& fm1, const Fresh& f0) {
#pragma unroll
    for (int j = 0; j < XV; j++) {
        s.Am[j] = fm1.A[j];  s.Ac[j] = f0.A[j];
        s.Ux[j] = fmaf(2.f, f0.Bx[j], fm1.Bx[j]);  s.Cx[j] = f0.Bx[j];
        s.Uy[j] = fmaf(2.f, f0.By[j], fm1.By[j]);  s.Cy[j] = f0.By[j];
    }
}

__device__ __forceinline__ void step_img(State& s, const Fresh& f, float msq[XV]) {
#pragma unroll
    for (int j = 0; j < XV; j++) {
        float gx = s.Ux[j] + f.Bx[j];
        float gy = s.Uy[j] + f.By[j];
        float gz = s.Am[j] - f.A[j];
        msq[j] = fmaf(gx, gx, fmaf(gy, gy, fmaf(gz, gz, 1e-10f)));
        s.Ux[j] = fmaf(2.f, f.Bx[j], s.Cx[j]);  s.Cx[j] = f.Bx[j];
        s.Uy[j] = fmaf(2.f, f.By[j], s.Cy[j]);  s.Cy[j] = f.By[j];
        s.Am[j] = s.Ac[j];                      s.Ac[j] = f.A[j];
    }
}

__global__ void __launch_bounds__(THREADS, 6)
k_loss(const float* __restrict__ pred,
       const float* __restrict__ gt,
       const float* __restrict__ mask,
       float* __restrict__ out) {
    __shared__ float smem[2 * BUF];

    const int tid = threadIdx.x;
    const int tx = tid & (TX - 1), ty = tid >> 4;

    int bb = blockIdx.x;
    const int xt = bb % NXT;  bb /= NXT;
    const int yt = bb % NYT;  bb /= NYT;
    const int zc = bb % NZ;
    const int b  = bb / NZ;
    const int bx0 = xt * XSPAN, by = yt * TY, z0 = zc * ZC;
    const int gy = by + ty, x0t = bx0 + tx * XV;

    const float* P = pred + (size_t)b * D * DS;
    const float* G = gt   + (size_t)b * D * DS;
    const float* M = mask + (size_t)b * D * DS;
    const int cell = gy * W + x0t;

    // Prologue: planes z0-1 and z0
    produce(smem, P, G, z0 - 1, by, bx0, tid);
    __syncthreads();
    State sP, sG;
    {
        Fresh fPm1 = consume(smem, 0, ty, tx);
        Fresh fGm1 = consume(smem, 1, ty, tx);
        produce(smem + BUF, P, G, z0, by, bx0, tid);
        __syncthreads();
        Fresh fP0 = consume(smem + BUF, 0, ty, tx);
        Fresh fG0 = consume(smem + BUF, 1, ty, tx);
        state_init(sP, fPm1, fP0);
        state_init(sG, fGm1, fG0);
    }

    float acc = 0.f;
#pragma unroll 2
    for (int c = z0; c < z0 + ZC; c++) {
        float* buf = smem + ((c - z0) & 1) * BUF;
        // mask for plane c: independent of smem, issue before the barrier
        float4 mv = __ldg(reinterpret_cast<const float4*>(M + c * DS + cell));
        produce(buf, P, G, c + 1, by, bx0, tid);
        __syncthreads();

        float msqP[XV], msqG[XV];
        { Fresh fP = consume(buf, 0, ty, tx); step_img(sP, fP, msqP); }
        { Fresh fG = consume(buf, 1, ty, tx); step_img(sG, fG, msqG); }

        // plane-c centers: loaded by this block last iter -> L1 hits
        float4 pv = __ldg(reinterpret_cast<const float4*>(P + c * DS + cell));
        float4 gv = __ldg(reinterpret_cast<const float4*>(G + c * DS + cell));

        const float pvj[XV] = { pv.x, pv.y, pv.z, pv.w };
        const float gvj[XV] = { gv.x, gv.y, gv.z, gv.w };
        const float mvj[XV] = { mv.x, mv.y, mv.z, mv.w };
#pragma unroll
        for (int j = 0; j < XV; j++) {
            float magp = fsqrt_a(msqP[j]);
            float magg = fsqrt_a(msqG[j]);
            float d    = pvj[j] - gvj[j];
            float mse  = d * d * mvj[j];
            float dm   = magg - magp;
            float mge  = dm * dm * mvj[j];
            acc += fmaf(htanh(mge), mse, mse);
        }
    }

    // Block reduction -> one fp64 atomic; last block finalizes + re-arms
#pragma unroll
    for (int o = 16; o; o >>= 1) acc += __shfl_xor_sync(0xffffffffu, acc, o);
    __shared__ float ws[THREADS / 32];
    int lane = tid & 31, wid = tid >> 5;
    if (lane == 0) ws[wid] = acc;
    __syncthreads();
    if (tid == 0) {
        float s = ws[0] + ws[1] + ws[2] + ws[3];
        atomicAdd(&g_accum, (double)s);
        __threadfence();
        unsigned tk = atomicAdd(&g_done, 1u);
        if (tk == (unsigned)gridDim.x - 1u) {
            double total = atomicAdd(&g_accum, 0.0);
            out[0] = (float)(total / (double)NVOX);
            g_accum = 0.0;
            g_done  = 0;
        }
    }
}

extern "C" void kernel_launch(void* const* d_in, const int* in_sizes, int n_in,
                              void* d_out, int out_size) {
    k_loss<<<NBLOCKS, THREADS>>>((const float*)d_in[0], (const float*)d_in[1],
                                 (const float*)d_in[2], (float*)d_out);
}

// round 6
// speedup vs baseline: 1.0408x; 1.0408x over previous
#include <cuda_runtime.h>

// Geometry fixed by the reference: (2,1,192,192,192) fp32 x3 -> scalar
constexpr int BATCH = 2, D = 192, H = 192, W = 192;
constexpr int DS = H * W;
constexpr int XV = 4;                  // x-values per pair (one float4)
constexpr int ZC = 16;                 // z planes per pair
constexpr int GX = W / XV;             // 48
constexpr int NZ = D / ZC;             // 12
constexpr int THREADS = 128;
constexpr long long NVOX = (long long)BATCH * D * H * W;
constexpr int NPAIRS  = GX * H * NZ * BATCH;       // 221184
constexpr int NBLOCKS = NPAIRS * 2 / THREADS;      // 3456

__device__ double   g_accum = 0.0;
__device__ unsigned g_done  = 0;

__device__ __forceinline__ float fsqrt_a(float x) {
    float y; asm("sqrt.approx.f32 %0, %1;" : "=f"(y) : "f"(x)); return y;
}
__device__ __forceinline__ float htanh(float x) {
    float y; asm("tanh.approx.f32 %0, %1;" : "=f"(y) : "f"(x)); return y;
}

struct Fresh { float A[XV], Bx[XV], By[XV]; };
// Streaming z-partials for ONE image (24 regs):
//   Am/Ac = A[c-1], A[c];  Ux/Cx = Bx[c-1]+2Bx[c], Bx[c];  Uy/Cy likewise.
struct State { float Am[XV], Ac[XV], Ux[XV], Cx[XV], Uy[XV], Cy[XV]; };

// x-pass for one row: s = [1,2,1]*x, d = x[+1]-x[-1], zero-padded OOB.
__device__ __forceinline__ void row_sd(const float* __restrict__ p, bool ok, bool xl, bool xr,
                                       float s[XV], float d[XV]) {
    float v0 = 0.f, v1 = 0.f, v2 = 0.f, v3 = 0.f, vm = 0.f, vp = 0.f;
    if (ok) {
        float4 c = __ldg(reinterpret_cast<const float4*>(p));
        v0 = c.x; v1 = c.y; v2 = c.z; v3 = c.w;
        if (xl) vm = __ldg(p - 1);
        if (xr) vp = __ldg(p + XV);
    }
    s[0] = fmaf(2.f, v0, vm + v1);
    s[1] = fmaf(2.f, v1, v0 + v2);
    s[2] = fmaf(2.f, v2, v1 + v3);
    s[3] = fmaf(2.f, v3, v2 + vp);
    d[0] = v1 - vm;
    d[1] = v2 - v0;
    d[2] = v3 - v1;
    d[3] = vp - v2;
}

// In-plane separable pass: fold rows (gy-1, gy, gy+1) of the plane whose
// center row is at pc.  A = sy(sx), By = dy(sx), Bx = sy(dx).
__device__ __forceinline__ Fresh plane_pass(const float* __restrict__ pc, bool zok,
                                            bool ymok, bool ypok, bool xl, bool xr) {
    float sa[XV], da[XV], sb[XV], db[XV], sc[XV], dc[XV];
    row_sd(pc - W, zok && ymok, xl, xr, sa, da);
    row_sd(pc,     zok,         xl, xr, sb, db);
    row_sd(pc + W, zok && ypok, xl, xr, sc, dc);
    Fresh f;
#pragma unroll
    for (int j = 0; j < XV; j++) {
        f.A[j]  = fmaf(2.f, sb[j], sa[j] + sc[j]);
        f.By[j] = sa[j] - sc[j];
        f.Bx[j] = fmaf(2.f, db[j], da[j] + dc[j]);
    }
    return f;
}

__device__ __forceinline__ void state_init(State& s, const Fresh& fm1, const Fresh& f0) {
#pragma unroll
    for (int j = 0; j < XV; j++) {
        s.Am[j] = fm1.A[j];  s.Ac[j] = f0.A[j];
        s.Ux[j] = fmaf(2.f, f0.Bx[j], fm1.Bx[j]);  s.Cx[j] = f0.Bx[j];
        s.Uy[j] = fmaf(2.f, f0.By[j], fm1.By[j]);  s.Cy[j] = f0.By[j];
    }
}

// z-combine at plane c given fresh plane c+1; advances streaming state.
__device__ __forceinline__ void step_img(State& s, const Fresh& f, float msq[XV]) {
#pragma unroll
    for (int j = 0; j < XV; j++) {
        float gx = s.Ux[j] + f.Bx[j];
        float gy = s.Uy[j] + f.By[j];
        float gz = s.Am[j] - f.A[j];
        msq[j] = fmaf(gx, gx, fmaf(gy, gy, fmaf(gz, gz, 1e-10f)));
        s.Ux[j] = fmaf(2.f, f.Bx[j], s.Cx[j]);  s.Cx[j] = f.Bx[j];
        s.Uy[j] = fmaf(2.f, f.By[j], s.Cy[j]);  s.Cy[j] = f.By[j];
        s.Am[j] = s.Ac[j];                      s.Ac[j] = f.A[j];
    }
}

__global__ void __launch_bounds__(THREADS, 7)
k_loss(const float* __restrict__ pred,
       const float* __restrict__ gt,
       const float* __restrict__ mask,
       float* __restrict__ out) {
    const int gtid = blockIdx.x * THREADS + threadIdx.x;
    const int im = gtid & 1;          // 0: pred, 1: gt
    const int pr = gtid >> 1;         // pair index
    int xg  = pr % GX;
    int tq  = pr / GX;
    int gy  = tq % H;  tq /= H;
    int zc  = tq % NZ;
    int b   = tq / NZ;
    const int x0 = xg * XV, z0 = zc * ZC;

    const bool ymok = (gy > 0), ypok = (gy < H - 1);
    const bool xl = (x0 > 0), xr = (x0 + XV < W);

    const float* ownBase = im ? gt : pred;
    const float* othBase = im ? pred : gt;
    const size_t cell = (size_t)b * D * DS + (size_t)gy * W + x0;

    const float* pI = ownBase + cell + (long long)(z0 - 1) * DS;  // own stencil walker
    const float* pO = othBase + cell + (long long)z0 * DS;        // other-image center
    const float* pM = mask    + cell + (long long)z0 * DS;        // mask center

    // Prologue: own image, planes z0-1 and z0
    Fresh fm1 = plane_pass(pI, z0 > 0, ymok, ypok, xl, xr);
    pI += DS;
    Fresh f0  = plane_pass(pI, true,  ymok, ypok, xl, xr);
    State st;
    state_init(st, fm1, f0);

    float acc = 0.f;
    for (int c = z0; c < z0 + ZC; c++) {
        pI += DS;                                  // own image, plane c+1
        Fresh f = plane_pass(pI, c + 1 < D, ymok, ypok, xl, xr);

        float msq[XV];
        step_img(st, f, msq);

        float mag[XV], omag[XV];
#pragma unroll
        for (int j = 0; j < XV; j++) mag[j] = fsqrt_a(msq[j]);
#pragma unroll
        for (int j = 0; j < XV; j++) omag[j] = __shfl_xor_sync(0xffffffffu, mag[j], 1);

        // plane-c centers: own was loaded last iter (L1 hit); other is the
        // partner lane's data but reloading hits L1 too (partner loaded it).
        float4 ov4 = __ldg(reinterpret_cast<const float4*>(pO));
        float4 sv4 = __ldg(reinterpret_cast<const float4*>(pI - DS));
        float4 mv4 = __ldg(reinterpret_cast<const float4*>(pM));
        pO += DS; pM += DS;

        const float ownv[XV] = { sv4.x, sv4.y, sv4.z, sv4.w };
        const float othv[XV] = { ov4.x, ov4.y, ov4.z, ov4.w };
        const float mv[XV]   = { mv4.x, mv4.y, mv4.z, mv4.w };

        // Each lane of the pair handles 2 of the 4 x-values.
#pragma unroll
        for (int jj = 0; jj < 2; jj++) {
            int j = 2 * im + jj;
            float d   = ownv[j] - othv[j];          // (pred-gt), sign-free (squared)
            float mse = d * d * mv[j];
            float dm  = mag[j] - omag[j];           // (magP-magG), sign-free
            float mge = dm * dm * mv[j];
            acc += fmaf(htanh(mge), mse, mse);
        }
    }

    // Block reduction -> one fp64 atomic; last block finalizes + re-arms
#pragma unroll
    for (int o = 16; o; o >>= 1) acc += __shfl_xor_sync(0xffffffffu, acc, o);
    __shared__ float ws[THREADS / 32];
    int lane = threadIdx.x & 31, wid = threadIdx.x >> 5;
    if (lane == 0) ws[wid] = acc;
    __syncthreads();
    if (threadIdx.x == 0) {
        float s = ws[0] + ws[1] + ws[2] + ws[3];
        atomicAdd(&g_accum, (double)s);
        __threadfence();
        unsigned tk = atomicAdd(&g_done, 1u);
        if (tk == (unsigned)gridDim.x - 1u) {
            double total = atomicAdd(&g_accum, 0.0);
            out[0] = (float)(total / (double)NVOX);
            g_accum = 0.0;
            g_done  = 0;
        }
    }
}

extern "C" void kernel_launch(void* const* d_in, const int* in_sizes, int n_in,
                              void* d_out, int out_size) {
    k_loss<<<NBLOCKS, THREADS>>>((const float*)d_in[0], (const float*)d_in[1],
                                 (const float*)d_in[2], (float*)d_out);
}